// round 11
// baseline (speedup 1.0000x reference)
#include <cuda_runtime.h>
#include <cuda_fp16.h>
#include <cstdint>

#define Bn  2
#define Cc  64
#define Hh  128
#define Ww  256
#define HW  (Hh*Ww)        // 32768
#define Kk  16
#define CHW (Cc*HW)        // 2097152

// ---------------- scratch (device globals; no allocation) ----------------
__device__ __align__(16) unsigned short g_x16[(size_t)4*HW*64]; // x pixel-major fp16 [img][px][ci]
__device__ __align__(16) unsigned short g_t1 [(size_t)4*HW*64]; // conv1 out (lrelu), pixel-major fp16
__device__ __align__(16) uint2 g_wfrag[2*36*8*32];              // per-lane mma B fragments [conv][kstep][ntile][lane]
__device__ float g_buf[4*CHW];     // resblock outputs, NCHW fp32
__device__ float g_Q  [Bn*HW*Cc];  // pixel-major (b, p, c)
__device__ float g_S  [Bn*HW*Cc];
__device__ float g_R  [Bn*HW*Cc];
__device__ float g_att[Bn*HW*Cc];  // attention output, pixel-major

__device__ __forceinline__ uint32_t smem_u32(const void* p) {
    uint32_t a;
    asm("{ .reg .u64 t; cvta.to.shared.u64 t, %1; cvt.u32.u64 %0, t; }" : "=r"(a) : "l"(p));
    return a;
}
__device__ __forceinline__ void ldmatrix_x4(uint32_t* r, uint32_t addr) {
    asm volatile("ldmatrix.sync.aligned.m8n8.x4.shared.b16 {%0,%1,%2,%3}, [%4];"
        : "=r"(r[0]), "=r"(r[1]), "=r"(r[2]), "=r"(r[3]) : "r"(addr));
}
__device__ __forceinline__ void mma16816(float* c, const uint32_t* a, uint2 b) {
    asm volatile("mma.sync.aligned.m16n8k16.row.col.f32.f16.f16.f32 "
        "{%0,%1,%2,%3}, {%4,%5,%6,%7}, {%8,%9}, {%0,%1,%2,%3};"
        : "+f"(c[0]), "+f"(c[1]), "+f"(c[2]), "+f"(c[3])
        : "r"(a[0]), "r"(a[1]), "r"(a[2]), "r"(a[3]), "r"(b.x), "r"(b.y));
}

// ================= pre-pass kernels =======================================
// NCHW fp32 -> pixel-major fp16 (g_x16), 4 images
__global__ __launch_bounds__(256)
void to_pm16_kernel(const float* __restrict__ xl, const float* __restrict__ xr)
{
    __shared__ unsigned short s[128*65];
    const int p0  = blockIdx.x * 128;
    const int img = blockIdx.y;
    const int tid = threadIdx.x;
    const float* src = (img < 2) ? (xl + (size_t)img*CHW) : (xr + (size_t)(img-2)*CHW);
    for (int idx = tid; idx < 64*128; idx += 256) {
        int ci = idx >> 7, px = idx & 127;
        s[px*65 + ci] = __half_as_ushort(__float2half_rn(src[ci*HW + p0 + px]));
    }
    __syncthreads();
    unsigned short* dst = g_x16 + ((size_t)img*HW + p0)*64;
    for (int idx = tid; idx < 64*128; idx += 256) {
        int px = idx >> 6, ci = idx & 63;
        dst[idx] = s[px*65 + ci];
    }
}

// conv3x3 weights -> per-lane mma.m16n8k16 B fragments (col-major B = W[k][co])
__global__ __launch_bounds__(256)
void wfrag_kernel(const float* __restrict__ w1, const float* __restrict__ w2)
{
    int idx = blockIdx.x*256 + threadIdx.x;     // [conv][kstep][ntile][lane]
    if (idx >= 2*36*8*32) return;
    int l     = idx & 31;
    int n     = (idx >> 5) & 7;
    int kstep = (idx >> 8) % 36;
    int conv  = idx / (36*8*32);
    const float* w = conv ? w2 : w1;
    int tap = kstep >> 2;                       // tap = r*3+s
    int co  = n*8 + (l >> 2);
    uint2 val;
    #pragma unroll
    for (int r = 0; r < 2; r++) {
        int kl0 = (l & 3)*2 + r*8;
        int ci0 = (kstep & 3)*16 + kl0;
        __half2 h = __floats2half2_rn(w[co*576 + ci0*9 + tap],
                                      w[co*576 + (ci0+1)*9 + tap]);
        ((uint32_t*)&val)[r] = *reinterpret_cast<uint32_t*>(&h);
    }
    g_wfrag[idx] = val;
}

// ================= HMMA conv3x3 ===========================================
// mode 0: g_x16 -> lrelu(conv) -> g_t1 (pixel-major fp16)
// mode 1: g_t1  -> conv + residual(x) -> g_buf (NCHW fp32)
// grid (Hh, 4 images); block 256 = 8 warps x 32px, each warp all 64 co.
// CTA covers one full 256-px image row. 32px/warp = 2 m16 A-tiles per B-load.
#define A_STRIDE 144                       // bytes per px row (conflict-free ldmatrix)
#define A_TILE   (258*A_STRIDE)            // 37152 B per input row (px -1..256)
#define SM_CONV  (3*A_TILE)                // 111456 B

__global__ __launch_bounds__(256, 2)
void conv_hmma_kernel(const float* __restrict__ xl, const float* __restrict__ xr, int mode)
{
    extern __shared__ char smem[];
    const uint32_t sbase = smem_u32(smem);
    const int tid  = threadIdx.x;
    const int wid  = tid >> 5;
    const int lane = tid & 31;
    const int row  = blockIdx.x;
    const int img  = blockIdx.y;

    // ---- A: 3 halo rows x 258 px x 64 ci fp16, stride 144B --------------
    {
        const unsigned short* sp = (mode == 0) ? g_x16 : g_t1;
        const uint4* src = (const uint4*)(sp + (size_t)img*HW*64);
        const uint4 z = make_uint4(0u,0u,0u,0u);
        for (int idx = tid; idx < 3*258*8; idx += 256) {
            int r   = idx / (258*8);
            int rem = idx - r*(258*8);
            int pxl = rem >> 3, j = rem & 7;
            int hh  = row - 1 + r;
            int w   = pxl - 1;
            uint4 v = ((unsigned)hh < (unsigned)Hh && (unsigned)w < (unsigned)Ww)
                        ? src[((size_t)hh*Ww + w)*8 + j] : z;
            *(uint4*)(smem + r*A_TILE + pxl*A_STRIDE + j*16) = v;
        }
    }
    __syncthreads();

    const int wp0 = wid*32;                  // px base for this warp
    float acc0[8][4], acc1[8][4];
    #pragma unroll
    for (int n = 0; n < 8; n++)
        #pragma unroll
        for (int q = 0; q < 4; q++) { acc0[n][q] = 0.f; acc1[n][q] = 0.f; }

    const uint2* bbase = g_wfrag + (size_t)mode*36*8*32 + lane;
    const uint32_t lmoff = (lane & 15)*A_STRIDE + (lane >> 4)*16;

    #pragma unroll
    for (int k = 0; k < 36; k++) {
        const int tap = k >> 2;
        const int r   = tap / 3, s = tap - 3*(tap/3);
        const int kc  = k & 3;
        uint2 b[8];
        const uint2* bk = bbase + k*256;
        #pragma unroll
        for (int n = 0; n < 8; n++) b[n] = bk[n*32];
        uint32_t a0[4], a1[4];
        const uint32_t ab = sbase + r*A_TILE + (wp0 + s)*A_STRIDE + kc*32 + lmoff;
        ldmatrix_x4(a0, ab);
        ldmatrix_x4(a1, ab + 16*A_STRIDE);
        #pragma unroll
        for (int n = 0; n < 8; n++) {
            mma16816(acc0[n], a0, b[n]);
            mma16816(acc1[n], a1, b[n]);
        }
    }

    // ---- epilogue --------------------------------------------------------
    const int pr0 = lane >> 2;               // row within m-tile (+8 for c2,c3)
    const int c0l = (lane & 3)*2;            // col pair base within ntile
    if (mode == 0) {
        unsigned short* dst = g_t1 + ((size_t)img*HW + (size_t)row*Ww)*64;
        #pragma unroll
        for (int m = 0; m < 2; m++) {
            const int pxa = wp0 + m*16 + pr0;
            float (*am)[4] = m ? acc1 : acc0;
            #pragma unroll
            for (int n = 0; n < 8; n++) {
                const int co = n*8 + c0l;
                float a0 = am[n][0], a1 = am[n][1], a2 = am[n][2], a3 = am[n][3];
                a0 = (a0 > 0.f) ? a0 : 0.1f*a0;  a1 = (a1 > 0.f) ? a1 : 0.1f*a1;
                a2 = (a2 > 0.f) ? a2 : 0.1f*a2;  a3 = (a3 > 0.f) ? a3 : 0.1f*a3;
                __half2 h01 = __floats2half2_rn(a0, a1);
                __half2 h23 = __floats2half2_rn(a2, a3);
                *(__half2*)(dst + (size_t)pxa*64 + co)     = h01;
                *(__half2*)(dst + (size_t)(pxa+8)*64 + co) = h23;
            }
        }
    } else {
        const float* res = (img < 2) ? (xl + (size_t)img*CHW) : (xr + (size_t)(img-2)*CHW);
        float* dst = g_buf + (size_t)img*CHW;
        #pragma unroll
        for (int m = 0; m < 2; m++) {
            const int pg = row*Ww + wp0 + m*16 + pr0;
            float (*am)[4] = m ? acc1 : acc0;
            #pragma unroll
            for (int n = 0; n < 8; n++) {
                const int co = n*8 + c0l;
                dst[(size_t)co*HW + pg]         = am[n][0] + res[(size_t)co*HW + pg];
                dst[(size_t)(co+1)*HW + pg]     = am[n][1] + res[(size_t)(co+1)*HW + pg];
                dst[(size_t)co*HW + pg + 8]     = am[n][2] + res[(size_t)co*HW + pg + 8];
                dst[(size_t)(co+1)*HW + pg + 8] = am[n][3] + res[(size_t)(co+1)*HW + pg + 8];
            }
        }
    }
}

// ---------------- conv1x1 Q/S/R (64->64 + bias), output pixel-major -------
__global__ __launch_bounds__(256, 2)
void conv1x1_qsr_kernel(const float* __restrict__ w1, const float* __restrict__ b1,
                        const float* __restrict__ w2, const float* __restrict__ b2,
                        const float* __restrict__ w3, const float* __restrict__ b3)
{
    __shared__ float s_in[64*128];   // [ci][px]
    __shared__ float s_w [32*64];    // [ci32][co]
    __shared__ float s_b [64];

    const int p0  = blockIdx.x * 128;
    const int b   = blockIdx.y;
    const int wch = blockIdx.z;      // 0=Q(left), 1=S(right), 2=R(right)
    const int tid = threadIdx.x, tx = tid & 31, ty = tid >> 5;

    const float* in; const float* wgt; const float* bias; float* out;
    if (wch == 0)      { in = g_buf + b*CHW;       wgt = w1; bias = b1; out = g_Q; }
    else if (wch == 1) { in = g_buf + (2+b)*CHW;   wgt = w2; bias = b2; out = g_S; }
    else               { in = g_buf + (2+b)*CHW;   wgt = w3; bias = b3; out = g_R; }
    out += (long)b*HW*Cc;

    for (int idx = tid; idx < 64*128; idx += 256) {
        int ci = idx >> 7, px = idx & 127;
        s_in[idx] = in[ci*HW + p0 + px];
    }
    if (tid < 64) s_b[tid] = bias[tid];

    float acc[8][4];
    #pragma unroll
    for (int i = 0; i < 8; i++)
        #pragma unroll
        for (int j = 0; j < 4; j++) acc[i][j] = 0.f;

    for (int cw = 0; cw < 2; cw++) {
        __syncthreads();
        for (int idx = tid; idx < 32*64; idx += 256) {
            int ci = idx >> 6, co = idx & 63;
            s_w[idx] = wgt[co*64 + cw*32 + ci];
        }
        __syncthreads();
        #pragma unroll 1
        for (int c = 0; c < 32; c++) {
            const int ci = cw*32 + c;
            float4 w0 = *(const float4*)&s_w[c*64 + ty*8];
            float4 w1v = *(const float4*)&s_w[c*64 + ty*8 + 4];
            float a[4];
            #pragma unroll
            for (int j = 0; j < 4; j++) a[j] = s_in[ci*128 + tx + 32*j];
            #pragma unroll
            for (int j = 0; j < 4; j++) {
                acc[0][j] += w0.x*a[j]; acc[1][j] += w0.y*a[j];
                acc[2][j] += w0.z*a[j]; acc[3][j] += w0.w*a[j];
                acc[4][j] += w1v.x*a[j]; acc[5][j] += w1v.y*a[j];
                acc[6][j] += w1v.z*a[j]; acc[7][j] += w1v.w*a[j];
            }
        }
    }

    #pragma unroll
    for (int j = 0; j < 4; j++) {
        const int p = p0 + tx + 32*j;
        float4 o0, o1;
        o0.x = acc[0][j] + s_b[ty*8+0]; o0.y = acc[1][j] + s_b[ty*8+1];
        o0.z = acc[2][j] + s_b[ty*8+2]; o0.w = acc[3][j] + s_b[ty*8+3];
        o1.x = acc[4][j] + s_b[ty*8+4]; o1.y = acc[5][j] + s_b[ty*8+5];
        o1.z = acc[6][j] + s_b[ty*8+6]; o1.w = acc[7][j] + s_b[ty*8+7];
        *(float4*)&out[(long)p*64 + ty*8]     = o0;
        *(float4*)&out[(long)p*64 + ty*8 + 4] = o1;
    }
}

// ---------------- attention: 16 lanes per pixel, 2 px per warp ------------
__global__ __launch_bounds__(256)
void attn_kernel(const int* __restrict__ xxs, const int* __restrict__ yys,
                 float* __restrict__ m_out)
{
    const int warp = threadIdx.x >> 5, lane = threadIdx.x & 31;
    const int half = lane >> 4, hl = lane & 15;
    const int pg = blockIdx.x*16 + warp*2 + half;   // b*HW + p
    const int b  = pg >> 15;                        // HW = 2^15

    const float4 q = ((const float4*)g_Q)[(size_t)pg*16 + hl];
    const int* xp = xxs + pg*Kk;
    const int* yp = yys + pg*Kk;
    const float4* Sb = (const float4*)(g_S + (size_t)b*HW*Cc);
    const float4* Rb = (const float4*)(g_R + (size_t)b*HW*Cc);

    int   fp[Kk];
    float sc[Kk];
    #pragma unroll
    for (int k = 0; k < Kk; k++) {
        int f = xp[k]*Ww + yp[k];
        fp[k] = f;
        float4 s4 = Sb[(size_t)f*16 + hl];
        float d = q.x*s4.x + q.y*s4.y + q.z*s4.z + q.w*s4.w;
        d += __shfl_xor_sync(0xffffffffu, d, 8);
        d += __shfl_xor_sync(0xffffffffu, d, 4);
        d += __shfl_xor_sync(0xffffffffu, d, 2);
        d += __shfl_xor_sync(0xffffffffu, d, 1);
        sc[k] = d;
    }
    float mx = sc[0];
    #pragma unroll
    for (int k = 1; k < Kk; k++) mx = fmaxf(mx, sc[k]);
    float sum = 0.f;
    #pragma unroll
    for (int k = 0; k < Kk; k++) { sc[k] = __expf(sc[k] - mx); sum += sc[k]; }
    const float inv = 1.f / sum;

    float4 acc = make_float4(0.f, 0.f, 0.f, 0.f);
    float  myM = 0.f;
    #pragma unroll
    for (int k = 0; k < Kk; k++) {
        float m = sc[k]*inv;
        float4 v = Rb[(size_t)fp[k]*16 + hl];
        acc.x += m*v.x; acc.y += m*v.y; acc.z += m*v.z; acc.w += m*v.w;
        if (hl == k) myM = m;
    }
    ((float4*)g_att)[(size_t)pg*16 + hl] = acc;
    m_out[(size_t)pg*Kk + hl] = myM;
}

// ---------------- fusion conv1x1 (128->64 + bias), NCHW output ------------
__global__ __launch_bounds__(256, 2)
void fuse_kernel(const float* __restrict__ xl,
                 const float* __restrict__ fw, const float* __restrict__ fb,
                 float* __restrict__ out)
{
    __shared__ float s_in[64*129];
    __shared__ float s_w [32*64];
    __shared__ float s_b [64];

    const int p0  = blockIdx.x * 128;
    const int b   = blockIdx.y;
    const int tid = threadIdx.x, tx = tid & 31, ty = tid >> 5;

    if (tid < 64) s_b[tid] = fb[tid];

    float acc[8][4];
    #pragma unroll
    for (int i = 0; i < 8; i++)
        #pragma unroll
        for (int j = 0; j < 4; j++) acc[i][j] = 0.f;

    for (int half = 0; half < 2; half++) {
        __syncthreads();
        if (half == 0) {
            const float* src = g_att + ((long)b*HW + p0)*64;
            for (int idx = tid; idx < 8192; idx += 256) {
                int px = idx >> 6, ci = idx & 63;
                s_in[ci*129 + px] = src[idx];
            }
        } else {
            const float* src = xl + (long)b*CHW;
            for (int idx = tid; idx < 8192; idx += 256) {
                int ci = idx >> 7, px = idx & 127;
                s_in[ci*129 + px] = src[ci*HW + p0 + px];
            }
        }
        for (int cw = 0; cw < 2; cw++) {
            __syncthreads();
            for (int idx = tid; idx < 32*64; idx += 256) {
                int ci = idx >> 6, co = idx & 63;
                s_w[idx] = fw[co*128 + half*64 + cw*32 + ci];
            }
            __syncthreads();
            #pragma unroll 1
            for (int c = 0; c < 32; c++) {
                const int ci = cw*32 + c;
                float4 w0 = *(const float4*)&s_w[c*64 + ty*8];
                float4 w1v = *(const float4*)&s_w[c*64 + ty*8 + 4];
                float a[4];
                #pragma unroll
                for (int j = 0; j < 4; j++) a[j] = s_in[ci*129 + tx + 32*j];
                #pragma unroll
                for (int j = 0; j < 4; j++) {
                    acc[0][j] += w0.x*a[j]; acc[1][j] += w0.y*a[j];
                    acc[2][j] += w0.z*a[j]; acc[3][j] += w0.w*a[j];
                    acc[4][j] += w1v.x*a[j]; acc[5][j] += w1v.y*a[j];
                    acc[6][j] += w1v.z*a[j]; acc[7][j] += w1v.w*a[j];
                }
            }
        }
    }

    float* dst = out + (long)b*Cc*HW + p0;
    #pragma unroll
    for (int i = 0; i < 8; i++) {
        const int co = ty*8 + i;
        const float bias = s_b[co];
        #pragma unroll
        for (int j = 0; j < 4; j++)
            dst[co*HW + tx + 32*j] = acc[i][j] + bias;
    }
}

// ---------------- launch ---------------------------------------------------
extern "C" void kernel_launch(void* const* d_in, const int* in_sizes, int n_in,
                              void* d_out, int out_size)
{
    const float* x_left  = (const float*)d_in[0];
    const float* x_right = (const float*)d_in[1];
    const int*   xxs     = (const int*)  d_in[2];
    const int*   yys     = (const int*)  d_in[3];
    const float* rb_w1   = (const float*)d_in[5];
    const float* rb_w2   = (const float*)d_in[6];
    const float* b1_w    = (const float*)d_in[7];
    const float* b1_b    = (const float*)d_in[8];
    const float* b2_w    = (const float*)d_in[9];
    const float* b2_b    = (const float*)d_in[10];
    const float* b3_w    = (const float*)d_in[11];
    const float* b3_b    = (const float*)d_in[12];
    const float* fus_w   = (const float*)d_in[13];
    const float* fus_b   = (const float*)d_in[14];

    float* out   = (float*)d_out;
    float* m_out = out + (long)Bn*Cc*HW;

    cudaFuncSetAttribute(conv_hmma_kernel, cudaFuncAttributeMaxDynamicSharedMemorySize, SM_CONV);

    wfrag_kernel<<<72, 256>>>(rb_w1, rb_w2);
    to_pm16_kernel<<<dim3(HW/128, 4), 256>>>(x_left, x_right);
    conv_hmma_kernel<<<dim3(Hh, 4), 256, SM_CONV>>>(x_left, x_right, 0);
    conv_hmma_kernel<<<dim3(Hh, 4), 256, SM_CONV>>>(x_left, x_right, 1);
    conv1x1_qsr_kernel<<<dim3(HW/128, Bn, 3), 256>>>(b1_w, b1_b, b2_w, b2_b, b3_w, b3_b);
    attn_kernel<<<(Bn*HW)/16, 256>>>(xxs, yys, m_out);
    fuse_kernel<<<dim3(HW/128, Bn), 256>>>(x_left, fus_w, fus_b, out);
}

// round 15
// speedup vs baseline: 1.2392x; 1.2392x over previous
#include <cuda_runtime.h>
#include <cuda_fp16.h>
#include <cstdint>

#define Bn  2
#define Cc  64
#define Hh  128
#define Ww  256
#define HW  (Hh*Ww)        // 32768
#define Kk  16
#define CHW (Cc*HW)        // 2097152

// ---------------- scratch (device globals; no allocation) ----------------
__device__ __align__(16) unsigned short g_x16[(size_t)4*HW*64]; // x pixel-major fp16 [img][px][ci]
__device__ __align__(16) unsigned short g_t1 [(size_t)4*HW*64]; // conv1 out (lrelu), pixel-major fp16
__device__ __align__(16) unsigned short g_bh [(size_t)4*HW*64]; // resblock out, fp16 hi, pixel-major
__device__ __align__(16) unsigned short g_bl [(size_t)4*HW*64]; // resblock out, fp16 lo residual
__device__ __align__(16) uint2 g_wfrag[2*36*8*32];              // conv3x3 B frags [conv][kstep][ntile][lane]
__device__ __align__(16) uint4 g_qwfrag[3*2*4*4*32];            // QSR W-as-A frags [wch][ws][mt][k][lane]
__device__ float g_Q  [Bn*HW*Cc];  // pixel-major (b, p, c)
__device__ float g_S  [Bn*HW*Cc];
__device__ float g_R  [Bn*HW*Cc];
__device__ float g_att[Bn*HW*Cc];  // attention output, pixel-major

__device__ __forceinline__ uint32_t smem_u32(const void* p) {
    uint32_t a;
    asm("{ .reg .u64 t; cvta.to.shared.u64 t, %1; cvt.u32.u64 %0, t; }" : "=r"(a) : "l"(p));
    return a;
}
__device__ __forceinline__ void ldmatrix_x4(uint32_t* r, uint32_t addr) {
    asm volatile("ldmatrix.sync.aligned.m8n8.x4.shared.b16 {%0,%1,%2,%3}, [%4];"
        : "=r"(r[0]), "=r"(r[1]), "=r"(r[2]), "=r"(r[3]) : "r"(addr));
}
__device__ __forceinline__ void ldmatrix_x2(uint32_t* r, uint32_t addr) {
    asm volatile("ldmatrix.sync.aligned.m8n8.x2.shared.b16 {%0,%1}, [%2];"
        : "=r"(r[0]), "=r"(r[1]) : "r"(addr));
}
__device__ __forceinline__ void mma16816(float* c, const uint32_t* a, uint2 b) {
    asm volatile("mma.sync.aligned.m16n8k16.row.col.f32.f16.f16.f32 "
        "{%0,%1,%2,%3}, {%4,%5,%6,%7}, {%8,%9}, {%0,%1,%2,%3};"
        : "+f"(c[0]), "+f"(c[1]), "+f"(c[2]), "+f"(c[3])
        : "r"(a[0]), "r"(a[1]), "r"(a[2]), "r"(a[3]), "r"(b.x), "r"(b.y));
}

// ================= pre-pass kernels =======================================
// NCHW fp32 -> pixel-major fp16 (g_x16), 4 images
__global__ __launch_bounds__(256)
void to_pm16_kernel(const float* __restrict__ xl, const float* __restrict__ xr)
{
    __shared__ unsigned short s[128*65];
    const int p0  = blockIdx.x * 128;
    const int img = blockIdx.y;
    const int tid = threadIdx.x;
    const float* src = (img < 2) ? (xl + (size_t)img*CHW) : (xr + (size_t)(img-2)*CHW);
    for (int idx = tid; idx < 64*128; idx += 256) {
        int ci = idx >> 7, px = idx & 127;
        s[px*65 + ci] = __half_as_ushort(__float2half_rn(src[ci*HW + p0 + px]));
    }
    __syncthreads();
    unsigned short* dst = g_x16 + ((size_t)img*HW + p0)*64;
    for (int idx = tid; idx < 64*128; idx += 256) {
        int px = idx >> 6, ci = idx & 63;
        dst[idx] = s[px*65 + ci];
    }
}

// conv3x3 weights -> per-lane mma B fragments (col-major B = W[k][co])
__global__ __launch_bounds__(256)
void wfrag_kernel(const float* __restrict__ w1, const float* __restrict__ w2)
{
    int idx = blockIdx.x*256 + threadIdx.x;     // [conv][kstep][ntile][lane]
    if (idx >= 2*36*8*32) return;
    int l     = idx & 31;
    int n     = (idx >> 5) & 7;
    int kstep = (idx >> 8) % 36;
    int conv  = idx / (36*8*32);
    const float* w = conv ? w2 : w1;
    int tap = kstep >> 2;                       // tap = r*3+s
    int co  = n*8 + (l >> 2);
    uint2 val;
    #pragma unroll
    for (int r = 0; r < 2; r++) {
        int kl0 = (l & 3)*2 + r*8;
        int ci0 = (kstep & 3)*16 + kl0;
        __half2 h = __floats2half2_rn(w[co*576 + ci0*9 + tap],
                                      w[co*576 + (ci0+1)*9 + tap]);
        ((uint32_t*)&val)[r] = *reinterpret_cast<uint32_t*>(&h);
    }
    g_wfrag[idx] = val;
}

// QSR 1x1 weights -> W-as-A m16k16 fragments, split hi/lo fp16
__global__ __launch_bounds__(256)
void qsr_wfrag_kernel(const float* __restrict__ w1, const float* __restrict__ w2,
                      const float* __restrict__ w3)
{
    int idx = blockIdx.x*256 + threadIdx.x;   // lane(5) k(2) mt(2) ws(1) wch
    if (idx >= 3*2*4*4*32) return;
    int lane = idx & 31;
    int k    = (idx >> 5) & 3;
    int mt   = (idx >> 7) & 3;
    int ws   = (idx >> 9) & 1;
    int wch  = idx >> 10;
    const float* w = (wch == 0) ? w1 : (wch == 1) ? w2 : w3;  // [co][ci]
    const int row = mt*16 + (lane >> 2);
    const int c0  = k*16 + (lane & 3)*2;
    uint4 val;
    uint32_t* vp = (uint32_t*)&val;
    #pragma unroll
    for (int q = 0; q < 4; q++) {
        int rr = row + (q & 1)*8;
        int cc = c0 + (q >> 1)*8;
        float v0 = w[rr*64 + cc], v1 = w[rr*64 + cc + 1];
        __half h0 = __float2half_rn(v0), h1 = __float2half_rn(v1);
        if (ws) { h0 = __float2half_rn(v0 - __half2float(h0));
                  h1 = __float2half_rn(v1 - __half2float(h1)); }
        __half2 h2 = __halves2half2(h0, h1);
        vp[q] = *reinterpret_cast<uint32_t*>(&h2);
    }
    g_qwfrag[idx] = val;
}

// ================= HMMA conv3x3 ===========================================
// mode 0: g_x16 -> lrelu(conv) -> g_t1 (pixel-major fp16)
// mode 1: g_t1  -> conv + residual(x) -> g_bh/g_bl (pixel-major fp16 split)
#define A_STRIDE 144
#define A_TILE   (258*A_STRIDE)            // 37152 B per input row (px -1..256)
#define SM_CONV  (3*A_TILE)                // 111456 B

__global__ __launch_bounds__(256, 2)
void conv_hmma_kernel(const float* __restrict__ xl, const float* __restrict__ xr, int mode)
{
    extern __shared__ char smem[];
    const uint32_t sbase = smem_u32(smem);
    const int tid  = threadIdx.x;
    const int wid  = tid >> 5;
    const int lane = tid & 31;
    const int row  = blockIdx.x;
    const int img  = blockIdx.y;

    {
        const unsigned short* sp = (mode == 0) ? g_x16 : g_t1;
        const uint4* src = (const uint4*)(sp + (size_t)img*HW*64);
        const uint4 z = make_uint4(0u,0u,0u,0u);
        for (int idx = tid; idx < 3*258*8; idx += 256) {
            int r   = idx / (258*8);
            int rem = idx - r*(258*8);
            int pxl = rem >> 3, j = rem & 7;
            int hh  = row - 1 + r;
            int w   = pxl - 1;
            uint4 v = ((unsigned)hh < (unsigned)Hh && (unsigned)w < (unsigned)Ww)
                        ? src[((size_t)hh*Ww + w)*8 + j] : z;
            *(uint4*)(smem + r*A_TILE + pxl*A_STRIDE + j*16) = v;
        }
    }
    __syncthreads();

    const int wp0 = wid*32;
    float acc0[8][4], acc1[8][4];
    #pragma unroll
    for (int n = 0; n < 8; n++)
        #pragma unroll
        for (int q = 0; q < 4; q++) { acc0[n][q] = 0.f; acc1[n][q] = 0.f; }

    const uint2* bbase = g_wfrag + (size_t)mode*36*8*32 + lane;
    const uint32_t lmoff = (lane & 15)*A_STRIDE + (lane >> 4)*16;

    #pragma unroll
    for (int k = 0; k < 36; k++) {
        const int tap = k >> 2;
        const int r   = tap / 3, s = tap - 3*(tap/3);
        const int kc  = k & 3;
        uint2 b[8];
        const uint2* bk = bbase + k*256;
        #pragma unroll
        for (int n = 0; n < 8; n++) b[n] = bk[n*32];
        uint32_t a0[4], a1[4];
        const uint32_t ab = sbase + r*A_TILE + (wp0 + s)*A_STRIDE + kc*32 + lmoff;
        ldmatrix_x4(a0, ab);
        ldmatrix_x4(a1, ab + 16*A_STRIDE);
        #pragma unroll
        for (int n = 0; n < 8; n++) {
            mma16816(acc0[n], a0, b[n]);
            mma16816(acc1[n], a1, b[n]);
        }
    }

    const int pr0 = lane >> 2;
    const int c0l = (lane & 3)*2;
    if (mode == 0) {
        unsigned short* dst = g_t1 + ((size_t)img*HW + (size_t)row*Ww)*64;
        #pragma unroll
        for (int m = 0; m < 2; m++) {
            const int pxa = wp0 + m*16 + pr0;
            float (*am)[4] = m ? acc1 : acc0;
            #pragma unroll
            for (int n = 0; n < 8; n++) {
                const int co = n*8 + c0l;
                float a0 = am[n][0], a1 = am[n][1], a2 = am[n][2], a3 = am[n][3];
                a0 = (a0 > 0.f) ? a0 : 0.1f*a0;  a1 = (a1 > 0.f) ? a1 : 0.1f*a1;
                a2 = (a2 > 0.f) ? a2 : 0.1f*a2;  a3 = (a3 > 0.f) ? a3 : 0.1f*a3;
                __half2 h01 = __floats2half2_rn(a0, a1);
                __half2 h23 = __floats2half2_rn(a2, a3);
                *(__half2*)(dst + (size_t)pxa*64 + co)     = h01;
                *(__half2*)(dst + (size_t)(pxa+8)*64 + co) = h23;
            }
        }
    } else {
        const float* res = (img < 2) ? (xl + (size_t)img*CHW) : (xr + (size_t)(img-2)*CHW);
        unsigned short* dh = g_bh + ((size_t)img*HW + (size_t)row*Ww)*64;
        unsigned short* dl = g_bl + ((size_t)img*HW + (size_t)row*Ww)*64;
        #pragma unroll
        for (int m = 0; m < 2; m++) {
            const int pxa = wp0 + m*16 + pr0;
            const int pg  = row*Ww + pxa;
            float (*am)[4] = m ? acc1 : acc0;
            #pragma unroll
            for (int n = 0; n < 8; n++) {
                const int co = n*8 + c0l;
                float v0 = am[n][0] + res[(size_t)co*HW + pg];
                float v1 = am[n][1] + res[(size_t)(co+1)*HW + pg];
                float v2 = am[n][2] + res[(size_t)co*HW + pg + 8];
                float v3 = am[n][3] + res[(size_t)(co+1)*HW + pg + 8];
                __half h0 = __float2half_rn(v0), h1 = __float2half_rn(v1);
                __half h2 = __float2half_rn(v2), h3 = __float2half_rn(v3);
                __half l0 = __float2half_rn(v0 - __half2float(h0));
                __half l1 = __float2half_rn(v1 - __half2float(h1));
                __half l2 = __float2half_rn(v2 - __half2float(h2));
                __half l3 = __float2half_rn(v3 - __half2float(h3));
                *(__half2*)(dh + (size_t)pxa*64 + co)     = __halves2half2(h0, h1);
                *(__half2*)(dh + (size_t)(pxa+8)*64 + co) = __halves2half2(h2, h3);
                *(__half2*)(dl + (size_t)pxa*64 + co)     = __halves2half2(l0, l1);
                *(__half2*)(dl + (size_t)(pxa+8)*64 + co) = __halves2half2(l2, l3);
            }
        }
    }
}

// ================= QSR conv1x1 via HMMA (W-as-A, split precision) =========
// grid (HW/128, Bn, 3 wch); block 256 = 8 warps = 4 co-mtiles x 2 px-halves.
// Mainloop: LDSM + HMMA only. Q/S/R written pixel-major fp32 + bias.
__global__ __launch_bounds__(256, 2)
void qsr_hmma_kernel(const float* __restrict__ b1, const float* __restrict__ b2,
                     const float* __restrict__ b3)
{
    __shared__ unsigned short s_h[128*72];   // [px][ci], 144B stride
    __shared__ unsigned short s_l[128*72];

    const int tid  = threadIdx.x;
    const int wid  = tid >> 5;
    const int lane = tid & 31;
    const int p0   = blockIdx.x * 128;
    const int b    = blockIdx.y;
    const int wch  = blockIdx.z;             // 0=Q(left) 1=S(right) 2=R(right)
    const int img  = (wch == 0) ? b : 2 + b;

    // stage pixel tiles (coalesced 128B rows -> 144B-stride smem)
    {
        const uint4* sh = (const uint4*)(g_bh + ((size_t)img*HW + p0)*64);
        const uint4* sl = (const uint4*)(g_bl + ((size_t)img*HW + p0)*64);
        for (int idx = tid; idx < 128*8; idx += 256) {
            int px = idx >> 3, j = idx & 7;
            *(uint4*)((char*)s_h + px*144 + j*16) = sh[idx];
            *(uint4*)((char*)s_l + px*144 + j*16) = sl[idx];
        }
    }

    const int mt = wid & 3;                  // co m-tile (16 co)
    const int pg = wid >> 2;                 // px half (64 px)

    // W fragments: hi + lo, 4 ksteps each, loaded once
    uint32_t wh[4][4], wl[4][4];
    {
        const uint4* fh = g_qwfrag + (((size_t)(wch*2 + 0)*4 + mt)*4)*32 + lane;
        const uint4* fl = g_qwfrag + (((size_t)(wch*2 + 1)*4 + mt)*4)*32 + lane;
        #pragma unroll
        for (int k = 0; k < 4; k++) {
            uint4 t = fh[k*32];
            wh[k][0] = t.x; wh[k][1] = t.y; wh[k][2] = t.z; wh[k][3] = t.w;
            uint4 u = fl[k*32];
            wl[k][0] = u.x; wl[k][1] = u.y; wl[k][2] = u.z; wl[k][3] = u.w;
        }
    }
    __syncthreads();

    float acc[8][4];
    #pragma unroll
    for (int n = 0; n < 8; n++)
        #pragma unroll
        for (int q = 0; q < 4; q++) acc[n][q] = 0.f;

    const uint32_t sbh = smem_u32(s_h), sbl = smem_u32(s_l);
    const uint32_t lrow = (pg*64 + (lane & 7)) * 144 + ((lane >> 3) & 1) * 16;

    #pragma unroll
    for (int n = 0; n < 8; n++) {
        const uint32_t noff = n*8*144 + lrow;
        #pragma unroll
        for (int k = 0; k < 4; k++) {
            uint32_t bh[2], bl2[2];
            ldmatrix_x2(bh,  sbh + noff + k*32);
            ldmatrix_x2(bl2, sbl + noff + k*32);
            uint2 ubh = make_uint2(bh[0], bh[1]);
            uint2 ubl = make_uint2(bl2[0], bl2[1]);
            mma16816(acc[n], wh[k], ubh);   // wh*h
            mma16816(acc[n], wh[k], ubl);   // wh*l
            mma16816(acc[n], wl[k], ubh);   // wl*h
        }
    }

    // epilogue: D[m=co][n=px] -> pixel-major fp32 + bias
    const float* bias = (wch == 0) ? b1 : (wch == 1) ? b2 : b3;
    const int co0 = mt*16 + (lane >> 2);
    const int co1 = co0 + 8;
    const float bs0 = bias[co0], bs1 = bias[co1];
    float* out = ((wch == 0) ? g_Q : (wch == 1) ? g_S : g_R)
               + ((size_t)b*HW + p0)*64;
    #pragma unroll
    for (int n = 0; n < 8; n++) {
        const int px0 = pg*64 + n*8 + (lane & 3)*2;
        out[(size_t)px0*64 + co0]       = acc[n][0] + bs0;
        out[(size_t)(px0+1)*64 + co0]   = acc[n][1] + bs0;
        out[(size_t)px0*64 + co1]       = acc[n][2] + bs1;
        out[(size_t)(px0+1)*64 + co1]   = acc[n][3] + bs1;
    }
}

// ---------------- attention: 16 lanes per pixel, 2 px per warp ------------
__global__ __launch_bounds__(256)
void attn_kernel(const int* __restrict__ xxs, const int* __restrict__ yys,
                 float* __restrict__ m_out)
{
    const int warp = threadIdx.x >> 5, lane = threadIdx.x & 31;
    const int half = lane >> 4, hl = lane & 15;
    const int pg = blockIdx.x*16 + warp*2 + half;   // b*HW + p
    const int b  = pg >> 15;                        // HW = 2^15

    const float4 q = ((const float4*)g_Q)[(size_t)pg*16 + hl];
    const int* xp = xxs + pg*Kk;
    const int* yp = yys + pg*Kk;
    const float4* Sb = (const float4*)(g_S + (size_t)b*HW*Cc);
    const float4* Rb = (const float4*)(g_R + (size_t)b*HW*Cc);

    int   fp[Kk];
    float sc[Kk];
    #pragma unroll
    for (int k = 0; k < Kk; k++) {
        int f = xp[k]*Ww + yp[k];
        fp[k] = f;
        float4 s4 = Sb[(size_t)f*16 + hl];
        float d = q.x*s4.x + q.y*s4.y + q.z*s4.z + q.w*s4.w;
        d += __shfl_xor_sync(0xffffffffu, d, 8);
        d += __shfl_xor_sync(0xffffffffu, d, 4);
        d += __shfl_xor_sync(0xffffffffu, d, 2);
        d += __shfl_xor_sync(0xffffffffu, d, 1);
        sc[k] = d;
    }
    float mx = sc[0];
    #pragma unroll
    for (int k = 1; k < Kk; k++) mx = fmaxf(mx, sc[k]);
    float sum = 0.f;
    #pragma unroll
    for (int k = 0; k < Kk; k++) { sc[k] = __expf(sc[k] - mx); sum += sc[k]; }
    const float inv = 1.f / sum;

    float4 acc = make_float4(0.f, 0.f, 0.f, 0.f);
    float  myM = 0.f;
    #pragma unroll
    for (int k = 0; k < Kk; k++) {
        float m = sc[k]*inv;
        float4 v = Rb[(size_t)fp[k]*16 + hl];
        acc.x += m*v.x; acc.y += m*v.y; acc.z += m*v.z; acc.w += m*v.w;
        if (hl == k) myM = m;
    }
    ((float4*)g_att)[(size_t)pg*16 + hl] = acc;
    m_out[(size_t)pg*Kk + hl] = myM;
}

// ---------------- fusion conv1x1 (128->64 + bias), NCHW output ------------
__global__ __launch_bounds__(256, 2)
void fuse_kernel(const float* __restrict__ xl,
                 const float* __restrict__ fw, const float* __restrict__ fb,
                 float* __restrict__ out)
{
    __shared__ float s_in[64*129];
    __shared__ float s_w [32*64];
    __shared__ float s_b [64];

    const int p0  = blockIdx.x * 128;
    const int b   = blockIdx.y;
    const int tid = threadIdx.x, tx = tid & 31, ty = tid >> 5;

    if (tid < 64) s_b[tid] = fb[tid];

    float acc[8][4];
    #pragma unroll
    for (int i = 0; i < 8; i++)
        #pragma unroll
        for (int j = 0; j < 4; j++) acc[i][j] = 0.f;

    for (int half = 0; half < 2; half++) {
        __syncthreads();
        if (half == 0) {
            const float* src = g_att + ((long)b*HW + p0)*64;
            for (int idx = tid; idx < 8192; idx += 256) {
                int px = idx >> 6, ci = idx & 63;
                s_in[ci*129 + px] = src[idx];
            }
        } else {
            const float* src = xl + (long)b*CHW;
            for (int idx = tid; idx < 8192; idx += 256) {
                int ci = idx >> 7, px = idx & 127;
                s_in[ci*129 + px] = src[ci*HW + p0 + px];
            }
        }
        for (int cw = 0; cw < 2; cw++) {
            __syncthreads();
            for (int idx = tid; idx < 32*64; idx += 256) {
                int ci = idx >> 6, co = idx & 63;
                s_w[idx] = fw[co*128 + half*64 + cw*32 + ci];
            }
            __syncthreads();
            #pragma unroll 1
            for (int c = 0; c < 32; c++) {
                const int ci = cw*32 + c;
                float4 w0 = *(const float4*)&s_w[c*64 + ty*8];
                float4 w1v = *(const float4*)&s_w[c*64 + ty*8 + 4];
                float a[4];
                #pragma unroll
                for (int j = 0; j < 4; j++) a[j] = s_in[ci*129 + tx + 32*j];
                #pragma unroll
                for (int j = 0; j < 4; j++) {
                    acc[0][j] += w0.x*a[j]; acc[1][j] += w0.y*a[j];
                    acc[2][j] += w0.z*a[j]; acc[3][j] += w0.w*a[j];
                    acc[4][j] += w1v.x*a[j]; acc[5][j] += w1v.y*a[j];
                    acc[6][j] += w1v.z*a[j]; acc[7][j] += w1v.w*a[j];
                }
            }
        }
    }

    float* dst = out + (long)b*Cc*HW + p0;
    #pragma unroll
    for (int i = 0; i < 8; i++) {
        const int co = ty*8 + i;
        const float bias = s_b[co];
        #pragma unroll
        for (int j = 0; j < 4; j++)
            dst[co*HW + tx + 32*j] = acc[i][j] + bias;
    }
}

// ---------------- launch ---------------------------------------------------
extern "C" void kernel_launch(void* const* d_in, const int* in_sizes, int n_in,
                              void* d_out, int out_size)
{
    const float* x_left  = (const float*)d_in[0];
    const float* x_right = (const float*)d_in[1];
    const int*   xxs     = (const int*)  d_in[2];
    const int*   yys     = (const int*)  d_in[3];
    const float* rb_w1   = (const float*)d_in[5];
    const float* rb_w2   = (const float*)d_in[6];
    const float* b1_w    = (const float*)d_in[7];
    const float* b1_b    = (const float*)d_in[8];
    const float* b2_w    = (const float*)d_in[9];
    const float* b2_b    = (const float*)d_in[10];
    const float* b3_w    = (const float*)d_in[11];
    const float* b3_b    = (const float*)d_in[12];
    const float* fus_w   = (const float*)d_in[13];
    const float* fus_b   = (const float*)d_in[14];

    float* out   = (float*)d_out;
    float* m_out = out + (long)Bn*Cc*HW;

    cudaFuncSetAttribute(conv_hmma_kernel, cudaFuncAttributeMaxDynamicSharedMemorySize, SM_CONV);

    wfrag_kernel<<<72, 256>>>(rb_w1, rb_w2);
    qsr_wfrag_kernel<<<12, 256>>>(b1_w, b2_w, b3_w);
    to_pm16_kernel<<<dim3(HW/128, 4), 256>>>(x_left, x_right);
    conv_hmma_kernel<<<dim3(Hh, 4), 256, SM_CONV>>>(x_left, x_right, 0);
    conv_hmma_kernel<<<dim3(Hh, 4), 256, SM_CONV>>>(x_left, x_right, 1);
    qsr_hmma_kernel<<<dim3(HW/128, Bn, 3), 256>>>(b1_b, b2_b, b3_b);
    attn_kernel<<<(Bn*HW)/16, 256>>>(xxs, yys, m_out);
    fuse_kernel<<<dim3(HW/128, Bn), 256>>>(x_left, fus_w, fus_b, out);
}